// round 1
// baseline (speedup 1.0000x reference)
#include <cuda_runtime.h>
#include <cuda_bf16.h>

#define BB 2
#define CC 16
#define NN 6912          // 72*96
#define JT 128           // j tile held in smem
#define JC 9             // j chunks (NN/JC = 768 = 6*JT)
#define BT 256           // threads per block (i per block)

// ---------------- scratch (no allocations allowed) ----------------
__device__ float  g_f1n[BB * NN * CC];   // normalized+masked features, [b][i][c]
__device__ float  g_f2n[BB * NN * CC];
__device__ float4 g_p1 [BB * NN];        // xyz1, w = |p|^2
__device__ float4 g_p2t[BB * NN];        // pose-transformed xyz2
__device__ float4 g_p2n[BB * NN];        // noisy xyz2
__device__ double g_acc[BB];             // sum (kt-kn)*dot  (unnormalized)
__device__ double g_sm1[BB], g_sm2[BB];
__device__ double g_fns;

__global__ void zero_kernel() {
    int t = threadIdx.x;
    if (t < BB) { g_acc[t] = 0.0; g_sm1[t] = 0.0; g_sm2[t] = 0.0; }
    if (t == 0) g_fns = 0.0;
}

__global__ void prep_kernel(const float* __restrict__ f1,
                            const float* __restrict__ f2,
                            const float* __restrict__ d1,
                            const float* __restrict__ d2,
                            const float* __restrict__ pose,
                            const float* __restrict__ yz1) {
    int gid = blockIdx.x * blockDim.x + threadIdx.x;   // exactly BB*NN threads
    int b = gid / NN, i = gid % NN;

    float dd1 = d1[gid], dd2 = d2[gid];
    float m1 = dd1 > 0.f ? 1.f : 0.f;
    float m2 = dd2 > 0.f ? 1.f : 0.f;

    float gx = yz1[i], gy = yz1[NN + i], gz = yz1[2 * NN + i];
    float x1 = gx * dd1, y1 = gy * dd1, z1 = gz * dd1;
    float x2 = gx * dd2, y2 = gy * dd2, z2 = gz * dd2;

    const float* P = pose + b * 16;
    float xt = P[0] * x2 + P[1] * y2 + P[2]  * z2 + P[3];
    float yt = P[4] * x2 + P[5] * y2 + P[6]  * z2 + P[7];
    float zt = P[8] * x2 + P[9] * y2 + P[10] * z2 + P[11];

    g_p1 [gid] = make_float4(x1, y1, z1, x1*x1 + y1*y1 + z1*z1);
    g_p2n[gid] = make_float4(x2, y2, z2, x2*x2 + y2*y2 + z2*z2);
    g_p2t[gid] = make_float4(xt, yt, zt, xt*xt + yt*yt + zt*zt);

    float a1[CC], a2[CC];
    float s1 = 0.f, s2 = 0.f;
#pragma unroll
    for (int c = 0; c < CC; c++) {
        float v = f1[(b * CC + c) * NN + i]; a1[c] = v; s1 += v * v;
        float w = f2[(b * CC + c) * NN + i]; a2[c] = w; s2 += w * w;
    }
    float n1 = sqrtf(s1), n2 = sqrtf(s2);
    float r1 = m1 / (n1 + 1e-8f), r2 = m2 / (n2 + 1e-8f);
#pragma unroll
    for (int c = 0; c < CC; c++) {
        g_f1n[gid * CC + c] = a1[c] * r1;
        g_f2n[gid * CC + c] = a2[c] * r2;
    }

    // warp-level reduce the 3 scalars (NN multiple of 32 -> b uniform in warp)
    float vm1 = m1, vm2 = m2, vf = 100.f * (n1 * m1 + n2 * m2);
#pragma unroll
    for (int o = 16; o > 0; o >>= 1) {
        vm1 += __shfl_down_sync(0xffffffffu, vm1, o);
        vm2 += __shfl_down_sync(0xffffffffu, vm2, o);
        vf  += __shfl_down_sync(0xffffffffu, vf,  o);
    }
    if ((threadIdx.x & 31) == 0) {
        atomicAdd(&g_sm1[b], (double)vm1);
        atomicAdd(&g_sm2[b], (double)vm2);
        atomicAdd(&g_fns,    (double)vf);
    }
}

__global__ __launch_bounds__(BT) void pair_kernel() {
    const int b    = blockIdx.z;
    const int i    = blockIdx.y * BT + threadIdx.x;
    const int base = b * NN;

    __shared__ float  sf [JT * CC];
    __shared__ float4 spt[JT];
    __shared__ float4 spn[JT];

    float f1r[CC];
#pragma unroll
    for (int c = 0; c < CC; c++) f1r[c] = g_f1n[(base + i) * CC + c];
    const float4 p1 = g_p1[base + i];

    float acc = 0.f;
    const int j0 = blockIdx.x * (NN / JC);

    for (int jt = 0; jt < NN / JC; jt += JT) {
        __syncthreads();
        const int jb = j0 + jt;
        for (int idx = threadIdx.x; idx < JT * CC; idx += BT)
            sf[idx] = g_f2n[(base + jb) * CC + idx];          // contiguous
        for (int idx = threadIdx.x; idx < JT; idx += BT) {
            spt[idx] = g_p2t[base + jb + idx];
            spn[idx] = g_p2n[base + jb + idx];
        }
        __syncthreads();

#pragma unroll 4
        for (int j = 0; j < JT; j++) {
            float dot = 0.f;
#pragma unroll
            for (int c = 0; c < CC; c++) dot += f1r[c] * sf[j * CC + c]; // smem broadcast
            const float4 pt = spt[j];
            const float4 pn = spn[j];
            float st = fmaxf(p1.w + pt.w - 2.f * (p1.x*pt.x + p1.y*pt.y + p1.z*pt.z), 0.f);
            float sn = fmaxf(p1.w + pn.w - 2.f * (p1.x*pn.x + p1.y*pn.y + p1.z*pn.z), 0.f);
            acc += (__expf(-10.f * st) - __expf(-10.f * sn)) * dot;
        }
    }

    // block reduction
#pragma unroll
    for (int o = 16; o > 0; o >>= 1) acc += __shfl_down_sync(0xffffffffu, acc, o);
    __shared__ float wsum[BT / 32];
    if ((threadIdx.x & 31) == 0) wsum[threadIdx.x >> 5] = acc;
    __syncthreads();
    if (threadIdx.x == 0) {
        float s = 0.f;
#pragma unroll
        for (int w = 0; w < BT / 32; w++) s += wsum[w];
        atomicAdd(&g_acc[b], (double)s);
    }
}

__global__ void finalize_kernel(float* __restrict__ out, int out_size) {
    int t = blockIdx.x * blockDim.x + threadIdx.x;
    if (t >= 3 && t < out_size) out[t] = 0.f;
    if (t == 0) {
        double total = 0.0;
        for (int b = 0; b < BB; b++)
            total += -g_acc[b] / (g_sm1[b] * g_sm2[b]);
        if (out_size > 0) out[0] = (float)total;   // final_loss sum
        if (out_size > 1) out[1] = (float)total;   // inner_neg sum (identical)
        if (out_size > 2) out[2] = (float)g_fns;   // fea_norm_sum * 100, summed
    }
}

extern "C" void kernel_launch(void* const* d_in, const int* in_sizes, int n_in,
                              void* d_out, int out_size) {
    const float* f1   = (const float*)d_in[0];
    const float* f2   = (const float*)d_in[1];
    const float* d1   = (const float*)d_in[2];
    const float* d2   = (const float*)d_in[3];
    const float* pose = (const float*)d_in[4];
    const float* yz1  = (const float*)d_in[7];
    float* out = (float*)d_out;

    zero_kernel<<<1, 32>>>();
    prep_kernel<<<(BB * NN) / 256, 256>>>(f1, f2, d1, d2, pose, yz1);
    pair_kernel<<<dim3(JC, NN / BT, BB), BT>>>();
    int fin_threads = out_size > 256 ? 256 : 256;
    int fin_blocks  = (out_size + 255) / 256; if (fin_blocks < 1) fin_blocks = 1;
    finalize_kernel<<<fin_blocks, fin_threads>>>(out, out_size);
}

// round 2
// speedup vs baseline: 2.7987x; 2.7987x over previous
#include <cuda_runtime.h>
#include <cuda_bf16.h>
#include <cstdint>

#define BB 2
#define CC 16
#define NN 6912          // 72*96
#define BT 128           // threads per block (4 warps)
#define MW 32            // i rows per warp
#define IT 128           // i rows per block
#define JCH 128          // j chunk in smem
#define JPAD 136         // padded j stride for bf16 tiles (bank-conflict-free)
#define JSPLIT 18
#define JBLK (NN / JSPLIT)   // 384 j per block

#define S1 14.426950408889634f   // 10*log2(e)
#define S2 28.853900817779268f   // 20*log2(e)

// ---------------- scratch ----------------
__device__ float4 g_p1s[BB * NN];            // (2S x1, 2S y1, 2S z1, e_c1)
__device__ float4 g_p2t[BB * NN];            // (xt, yt, zt, -S|pt|^2)
__device__ float4 g_p2n[BB * NN];            // (x2, y2, z2, -S|p2|^2)
__device__ float  g_f1e[BB * NN * CC];       // f1 normalized*mask*e_c1, [b][i][c]
__device__ unsigned short g_f2h[BB * CC * NN];  // bf16 hi of f2n, [b][c][j]
__device__ unsigned short g_f2l[BB * CC * NN];  // bf16 lo
__device__ double g_acc[BB];
__device__ double g_sm1[BB], g_sm2[BB];
__device__ double g_fns;

// ---------------- helpers ----------------
__device__ __forceinline__ float ex2f(float x) {
    float r; asm("ex2.approx.ftz.f32 %0, %1;" : "=f"(r) : "f"(x)); return r;
}
__device__ __forceinline__ unsigned short bf16_bits(float v) {
    unsigned short u; asm("cvt.rn.bf16.f32 %0, %1;" : "=h"(u) : "f"(v)); return u;
}
__device__ __forceinline__ float bf16_val(unsigned short u) {
    return __uint_as_float(((uint32_t)u) << 16);
}
// pack {lo, hi} floats into bf16x2 (lo -> low 16 bits)
__device__ __forceinline__ uint32_t pack_bf2(float lo, float hi) {
    uint32_t r; asm("cvt.rn.bf16x2.f32 %0, %1, %2;" : "=r"(r) : "f"(hi), "f"(lo)); return r;
}
// split two fp32 into bf16 hi pair + bf16 lo (residual) pair
__device__ __forceinline__ void split2(float d0, float d1, uint32_t& h, uint32_t& l) {
    h = pack_bf2(d0, d1);
    float h0 = __uint_as_float(h << 16);
    float h1 = __uint_as_float(h & 0xFFFF0000u);
    l = pack_bf2(d0 - h0, d1 - h1);
}
// D' = 2^(c2t + 2S p1.pt) - 2^(c2n + 2S p1.pn)   (c1 factored out)
__device__ __forceinline__ float dpair(float4 P, float4 pt, float4 pn) {
    float et = ex2f(fmaf(P.x, pt.x, fmaf(P.y, pt.y, fmaf(P.z, pt.z, pt.w))));
    float en = ex2f(fmaf(P.x, pn.x, fmaf(P.y, pn.y, fmaf(P.z, pn.z, pn.w))));
    return et - en;
}
__device__ __forceinline__ void mma_bf16(float* c, const uint32_t* a, const uint32_t* b) {
    asm volatile(
        "mma.sync.aligned.m16n8k16.row.col.f32.bf16.bf16.f32 "
        "{%0,%1,%2,%3}, {%4,%5,%6,%7}, {%8,%9}, {%0,%1,%2,%3};"
        : "+f"(c[0]), "+f"(c[1]), "+f"(c[2]), "+f"(c[3])
        : "r"(a[0]), "r"(a[1]), "r"(a[2]), "r"(a[3]), "r"(b[0]), "r"(b[1]));
}

// ---------------- kernels ----------------
__global__ void zero_kernel() {
    int t = threadIdx.x;
    if (t < BB) { g_acc[t] = 0.0; g_sm1[t] = 0.0; g_sm2[t] = 0.0; }
    if (t == 0) g_fns = 0.0;
}

__global__ void prep_kernel(const float* __restrict__ f1,
                            const float* __restrict__ f2,
                            const float* __restrict__ d1,
                            const float* __restrict__ d2,
                            const float* __restrict__ pose,
                            const float* __restrict__ yz1) {
    int gid = blockIdx.x * blockDim.x + threadIdx.x;   // BB*NN threads
    int b = gid / NN, i = gid % NN;

    float dd1 = d1[gid], dd2 = d2[gid];
    float m1 = dd1 > 0.f ? 1.f : 0.f;
    float m2 = dd2 > 0.f ? 1.f : 0.f;

    float gx = yz1[i], gy = yz1[NN + i], gz = yz1[2 * NN + i];
    float x1 = gx * dd1, y1 = gy * dd1, z1 = gz * dd1;
    float x2 = gx * dd2, y2 = gy * dd2, z2 = gz * dd2;

    const float* Pm = pose + b * 16;
    float xt = Pm[0]*x2 + Pm[1]*y2 + Pm[2] *z2 + Pm[3];
    float yt = Pm[4]*x2 + Pm[5]*y2 + Pm[6] *z2 + Pm[7];
    float zt = Pm[8]*x2 + Pm[9]*y2 + Pm[10]*z2 + Pm[11];

    float q1 = x1*x1 + y1*y1 + z1*z1;
    float e1 = ex2f(-S1 * q1);                       // 2^{c1}
    g_p1s[gid] = make_float4(S2*x1, S2*y1, S2*z1, e1);
    g_p2t[gid] = make_float4(xt, yt, zt, -S1*(xt*xt + yt*yt + zt*zt));
    g_p2n[gid] = make_float4(x2, y2, z2, -S1*(x2*x2 + y2*y2 + z2*z2));

    float a1[CC], a2[CC];
    float s1 = 0.f, s2 = 0.f;
#pragma unroll
    for (int c = 0; c < CC; c++) {
        float v = f1[(b * CC + c) * NN + i]; a1[c] = v; s1 += v * v;
        float w = f2[(b * CC + c) * NN + i]; a2[c] = w; s2 += w * w;
    }
    float n1 = sqrtf(s1), n2 = sqrtf(s2);
    float r1 = m1 / (n1 + 1e-8f), r2 = m2 / (n2 + 1e-8f);
#pragma unroll
    for (int c = 0; c < CC; c++) {
        g_f1e[gid * CC + c] = a1[c] * r1 * e1;       // fold 2^{c1} into f1
        float w = a2[c] * r2;
        unsigned short hb = bf16_bits(w);
        float hv = bf16_val(hb);
        g_f2h[(b * CC + c) * NN + i] = hb;
        g_f2l[(b * CC + c) * NN + i] = bf16_bits(w - hv);
    }

    float vm1 = m1, vm2 = m2, vf = 100.f * (n1 * m1 + n2 * m2);
#pragma unroll
    for (int o = 16; o > 0; o >>= 1) {
        vm1 += __shfl_down_sync(0xffffffffu, vm1, o);
        vm2 += __shfl_down_sync(0xffffffffu, vm2, o);
        vf  += __shfl_down_sync(0xffffffffu, vf,  o);
    }
    if ((threadIdx.x & 31) == 0) {
        atomicAdd(&g_sm1[b], (double)vm1);
        atomicAdd(&g_sm2[b], (double)vm2);
        atomicAdd(&g_fns,    (double)vf);
    }
}

__global__ __launch_bounds__(BT) void pair_kernel() {
    const int b    = blockIdx.z;
    const int base = b * NN;
    const int ibase = blockIdx.y * IT;
    const int warp = threadIdx.x >> 5, lane = threadIdx.x & 31;
    const int r = lane >> 2, cq = lane & 3;          // groupID, tid-in-group

    __shared__ float4 spt[JCH], spn[JCH];
    __shared__ unsigned short sfh[CC][JPAD], sfl[CC][JPAD];
    __shared__ float wred[BT / 32];

    // this lane's 4 p1 rows (rows r, r+8 of each 16-row A fragment)
    float4 P[4];
#pragma unroll
    for (int t = 0; t < 4; t++)
        P[t] = g_p1s[base + ibase + warp * MW + 8 * t + r];

    float acc[2][2][4];                              // [rowfrag][nhalf][4]
#pragma unroll
    for (int a = 0; a < 2; a++)
#pragma unroll
        for (int n = 0; n < 2; n++)
#pragma unroll
            for (int k = 0; k < 4; k++) acc[a][n][k] = 0.f;

    for (int ch = 0; ch < JBLK / JCH; ch++) {
        const int j0 = blockIdx.x * JBLK + ch * JCH;
        __syncthreads();
        for (int idx = threadIdx.x; idx < JCH; idx += BT) {
            spt[idx] = g_p2t[base + j0 + idx];
            spn[idx] = g_p2n[base + j0 + idx];
        }
        for (int idx = threadIdx.x; idx < CC * (JCH / 2); idx += BT) {
            int c = idx >> 6, jj = idx & 63;
            ((uint32_t*)&sfh[c][0])[jj] = ((const uint32_t*)(g_f2h + (b * CC + c) * NN + j0))[jj];
            ((uint32_t*)&sfl[c][0])[jj] = ((const uint32_t*)(g_f2l + (b * CC + c) * NN + j0))[jj];
        }
        __syncthreads();

#pragma unroll 1
        for (int ks = 0; ks < JCH / 16; ks++) {
            const int kb = ks * 16 + 2 * cq;
            float4 pt0 = spt[kb], pt1 = spt[kb + 1], pt8 = spt[kb + 8], pt9 = spt[kb + 9];
            float4 pn0 = spn[kb], pn1 = spn[kb + 1], pn8 = spn[kb + 8], pn9 = spn[kb + 9];

            uint32_t bh[2][2], bl[2][2];
#pragma unroll
            for (int nh = 0; nh < 2; nh++) {
                bh[nh][0] = *(const uint32_t*)&sfh[nh * 8 + r][kb];
                bh[nh][1] = *(const uint32_t*)&sfh[nh * 8 + r][kb + 8];
                bl[nh][0] = *(const uint32_t*)&sfl[nh * 8 + r][kb];
                bl[nh][1] = *(const uint32_t*)&sfl[nh * 8 + r][kb + 8];
            }
#pragma unroll
            for (int rf = 0; rf < 2; rf++) {
                float4 A0 = P[2 * rf], A1 = P[2 * rf + 1];
                float d00 = dpair(A0, pt0, pn0), d01 = dpair(A0, pt1, pn1);
                float d10 = dpair(A1, pt0, pn0), d11 = dpair(A1, pt1, pn1);
                float d08 = dpair(A0, pt8, pn8), d09 = dpair(A0, pt9, pn9);
                float d18 = dpair(A1, pt8, pn8), d19 = dpair(A1, pt9, pn9);
                uint32_t ah[4], al[4];
                split2(d00, d01, ah[0], al[0]);
                split2(d10, d11, ah[1], al[1]);
                split2(d08, d09, ah[2], al[2]);
                split2(d18, d19, ah[3], al[3]);
#pragma unroll
                for (int nh = 0; nh < 2; nh++) {
                    mma_bf16(acc[rf][nh], ah, bh[nh]);
                    mma_bf16(acc[rf][nh], ah, bl[nh]);
                    mma_bf16(acc[rf][nh], al, bh[nh]);
                }
            }
        }
    }

    // epilogue: contract C with f1e (e_c1 already folded in)
    float tot = 0.f;
#pragma unroll
    for (int rf = 0; rf < 2; rf++) {
#pragma unroll
        for (int nh = 0; nh < 2; nh++) {
            const float* F0 = g_f1e + (base + ibase + warp * MW + rf * 16 + r) * CC + nh * 8 + 2 * cq;
            const float* F1 = F0 + 8 * CC;
            tot += acc[rf][nh][0] * F0[0] + acc[rf][nh][1] * F0[1]
                 + acc[rf][nh][2] * F1[0] + acc[rf][nh][3] * F1[1];
        }
    }
#pragma unroll
    for (int o = 16; o > 0; o >>= 1) tot += __shfl_down_sync(0xffffffffu, tot, o);
    if (lane == 0) wred[warp] = tot;
    __syncthreads();
    if (threadIdx.x == 0) {
        float s = wred[0] + wred[1] + wred[2] + wred[3];
        atomicAdd(&g_acc[b], (double)s);
    }
}

__global__ void finalize_kernel(float* __restrict__ out, int out_size) {
    int t = blockIdx.x * blockDim.x + threadIdx.x;
    if (t >= 3 && t < out_size) out[t] = 0.f;
    if (t == 0) {
        double total = 0.0;
        for (int b = 0; b < BB; b++)
            total += -g_acc[b] / (g_sm1[b] * g_sm2[b]);
        if (out_size > 0) out[0] = (float)total;
        if (out_size > 1) out[1] = (float)total;
        if (out_size > 2) out[2] = (float)g_fns;
    }
}

extern "C" void kernel_launch(void* const* d_in, const int* in_sizes, int n_in,
                              void* d_out, int out_size) {
    const float* f1   = (const float*)d_in[0];
    const float* f2   = (const float*)d_in[1];
    const float* d1   = (const float*)d_in[2];
    const float* d2   = (const float*)d_in[3];
    const float* pose = (const float*)d_in[4];
    const float* yz1  = (const float*)d_in[7];
    float* out = (float*)d_out;

    zero_kernel<<<1, 32>>>();
    prep_kernel<<<(BB * NN) / 256, 256>>>(f1, f2, d1, d2, pose, yz1);
    pair_kernel<<<dim3(JSPLIT, NN / IT, BB), BT>>>();
    int fin_blocks = (out_size + 255) / 256; if (fin_blocks < 1) fin_blocks = 1;
    finalize_kernel<<<fin_blocks, 256>>>(out, out_size);
}